// round 1
// baseline (speedup 1.0000x reference)
#include <cuda_runtime.h>

#define TPB     256
#define NLAYERS 5
#define H       32
#define E       32
#define G       96   // 3*H

typedef unsigned long long ull;

// ---- packed f32x2 helpers (sm_103a) ----
__device__ __forceinline__ ull pack2(float lo, float hi) {
    ull r; asm("mov.b64 %0, {%1, %2};" : "=l"(r) : "f"(lo), "f"(hi)); return r;
}
__device__ __forceinline__ void unpack2(ull v, float& lo, float& hi) {
    asm("mov.b64 {%0, %1}, %2;" : "=f"(lo), "=f"(hi) : "l"(v));
}
__device__ __forceinline__ ull fma2(ull a, ull b, ull c) {
    ull d; asm("fma.rn.f32x2 %0, %1, %2, %3;" : "=l"(d) : "l"(a), "l"(b), "l"(c)); return d;
}
__device__ __forceinline__ float rcpa(float x) {
    float r; asm("rcp.approx.f32 %0, %1;" : "=f"(r) : "f"(x)); return r;
}
__device__ __forceinline__ float ex2a(float x) {
    float r; asm("ex2.approx.f32 %0, %1;" : "=f"(r) : "f"(x)); return r;
}
// sigmoid(x) = 1 / (1 + 2^(-x*log2e))
__device__ __forceinline__ float sigm(float x) {
    return rcpa(1.0f + ex2a(-1.442695041f * x));
}
// tanh(x) = 2*sigmoid(2x) - 1
__device__ __forceinline__ float tanh_(float x) {
    return fmaf(2.0f, rcpa(1.0f + ex2a(-2.885390082f * x)), -1.0f);
}

// Shared memory layout (in ull units)
#define SM_WD   0                      // 5*96*32 = 15360  dup w_ih
#define SM_BRZ  (SM_WD  + NLAYERS*G*H) // 5*64 = 320       dup (b_ih+b_hh) for r,z rows
#define SM_BN   (SM_BRZ + NLAYERS*2*H) // 5*32 = 160       dup b_ih (n rows)
#define SM_BHN  (SM_BN  + NLAYERS*H)   // 5*32 = 160       dup b_hh (n rows)
#define SM_FW   (SM_BHN + NLAYERS*H)   // 32*32 = 1024     dup fc_w
#define SM_FB   (SM_FW  + E*H)         // 32               dup fc_b
#define SM_HB   (SM_FB  + E)           // 32*256 = 8192    per-thread h bounce buf
#define SM_ULLS (SM_HB  + H*TPB)
#define SMEM_BYTES (SM_ULLS * sizeof(ull))  // 201,984 B

__global__ void __launch_bounds__(TPB, 1) gru_fused(
    const float* __restrict__ x,
    const float* __restrict__ w_ih,
    const float* __restrict__ b_ih,
    const float* __restrict__ b_hh,
    const float* __restrict__ fc_w,
    const float* __restrict__ fc_b,
    float* __restrict__ out)
{
    extern __shared__ ull sm[];
    ull* WD  = sm + SM_WD;
    ull* BRZ = sm + SM_BRZ;
    ull* BN  = sm + SM_BN;
    ull* BHN = sm + SM_BHN;
    ull* FW  = sm + SM_FW;
    ull* FB  = sm + SM_FB;
    ull* HB  = sm + SM_HB;

    const int tid = threadIdx.x;

    // ---- cooperative weight preload, duplicated for f32x2 ----
    for (int i = tid; i < NLAYERS * G * H; i += TPB) {
        float w = w_ih[i]; WD[i] = pack2(w, w);
    }
    for (int i = tid; i < NLAYERS * 2 * H; i += TPB) {
        int l = i / (2 * H), j = i - l * 2 * H;
        float v = b_ih[l * G + j] + b_hh[l * G + j];
        BRZ[i] = pack2(v, v);
    }
    for (int i = tid; i < NLAYERS * H; i += TPB) {
        int l = i / H, j = i - l * H;
        float vn = b_ih[l * G + 2 * H + j];
        float vh = b_hh[l * G + 2 * H + j];
        BN[i]  = pack2(vn, vn);
        BHN[i] = pack2(vh, vh);
    }
    for (int i = tid; i < E * H; i += TPB) {
        float w = fc_w[i]; FW[i] = pack2(w, w);
    }
    if (tid < E) { float v = fc_b[tid]; FB[tid] = pack2(v, v); }
    __syncthreads();

    // ---- two batch elements per thread, packed lo/hi ----
    const size_t b0 = (size_t)blockIdx.x * (2 * TPB) + tid;
    const size_t b1 = b0 + TPB;

    ull v[H];
    {
        const float4* xa = (const float4*)(x + b0 * E);
        const float4* xb = (const float4*)(x + b1 * E);
#pragma unroll
        for (int k = 0; k < E / 4; k++) {
            float4 a = xa[k], b = xb[k];
            v[4 * k + 0] = pack2(a.x, b.x);
            v[4 * k + 1] = pack2(a.y, b.y);
            v[4 * k + 2] = pack2(a.z, b.z);
            v[4 * k + 3] = pack2(a.w, b.w);
        }
    }

    // ---- 5 fused GRU layers (h_in = 0 so only b_hh survives from the hh path) ----
    for (int l = 0; l < NLAYERS; l++) {
        const ull* W   = WD  + l * G * H;
        const ull* Brz = BRZ + l * 2 * H;
        const ull* Bn  = BN  + l * H;
        const ull* Bh  = BHN + l * H;
#pragma unroll 2
        for (int j = 0; j < H; j++) {
            ull ar = Brz[j];
            ull az = Brz[H + j];
            ull an = Bn[j];
            const ulonglong2* Wr = (const ulonglong2*)(W + (size_t)j * H);
            const ulonglong2* Wz = (const ulonglong2*)(W + (size_t)(H + j) * H);
            const ulonglong2* Wn = (const ulonglong2*)(W + (size_t)(2 * H + j) * H);
#pragma unroll
            for (int i = 0; i < H / 2; i++) {
                ulonglong2 wr = Wr[i];
                ulonglong2 wz = Wz[i];
                ulonglong2 wn = Wn[i];
                ar = fma2(wr.x, v[2 * i], ar); ar = fma2(wr.y, v[2 * i + 1], ar);
                az = fma2(wz.x, v[2 * i], az); az = fma2(wz.y, v[2 * i + 1], az);
                an = fma2(wn.x, v[2 * i], an); an = fma2(wn.y, v[2 * i + 1], an);
            }
            float r0, r1, z0, z1, n0, n1;
            unpack2(ar, r0, r1);
            unpack2(az, z0, z1);
            r0 = sigm(r0); r1 = sigm(r1);
            z0 = sigm(z0); z1 = sigm(z1);
            an = fma2(pack2(r0, r1), Bh[j], an);
            unpack2(an, n0, n1);
            n0 = tanh_(n0); n1 = tanh_(n1);
            float h0 = (1.0f - z0) * n0;
            float h1 = (1.0f - z1) * n1;
            HB[j * TPB + tid] = pack2(h0, h1);   // lane-contiguous: conflict-free
        }
#pragma unroll
        for (int j = 0; j < H; j++) v[j] = HB[j * TPB + tid];
    }

    // ---- FC epilogue: out = fc_w · h + fc_b ----
#pragma unroll 2
    for (int e = 0; e < E; e++) {
        ull acc = FB[e];
        const ulonglong2* Fw = (const ulonglong2*)(FW + (size_t)e * H);
#pragma unroll
        for (int i = 0; i < H / 2; i++) {
            ulonglong2 w = Fw[i];
            acc = fma2(w.x, v[2 * i], acc);
            acc = fma2(w.y, v[2 * i + 1], acc);
        }
        float o0, o1;
        unpack2(acc, o0, o1);
        out[b0 * E + e] = o0;
        out[b1 * E + e] = o1;
    }
}

extern "C" void kernel_launch(void* const* d_in, const int* in_sizes, int n_in,
                              void* d_out, int out_size)
{
    const float* x    = (const float*)d_in[0];
    const float* w_ih = (const float*)d_in[1];
    // d_in[2] = w_hh: provably unused (h0 == 0 for every layer)
    const float* b_ih = (const float*)d_in[3];
    const float* b_hh = (const float*)d_in[4];
    const float* fc_w = (const float*)d_in[5];
    const float* fc_b = (const float*)d_in[6];
    float* out = (float*)d_out;

    const int B = in_sizes[0] / E;          // 1,048,576
    cudaFuncSetAttribute(gru_fused, cudaFuncAttributeMaxDynamicSharedMemorySize,
                         (int)SMEM_BYTES);
    const int grid = B / (2 * TPB);         // 2048 blocks, exact
    gru_fused<<<grid, TPB, SMEM_BYTES>>>(x, w_ih, b_ih, b_hh, fc_w, fc_b, out);
}

// round 4
// speedup vs baseline: 1.4906x; 1.4906x over previous
#include <cuda_runtime.h>

#define TPB     256
#define NLAYERS 5
#define H       32
#define E       32

typedef unsigned long long ull;

// ---- packed f32x2 helpers (sm_103a) ----
__device__ __forceinline__ void unpack2(ull v, float& lo, float& hi) {
    asm("mov.b64 {%0, %1}, %2;" : "=f"(lo), "=f"(hi) : "l"(v));
}
__device__ __forceinline__ ull fma2(ull a, ull b, ull c) {
    ull d; asm("fma.rn.f32x2 %0, %1, %2, %3;" : "=l"(d) : "l"(a), "l"(b), "l"(c)); return d;
}
__device__ __forceinline__ float rcpa(float x) {
    float r; asm("rcp.approx.f32 %0, %1;" : "=f"(r) : "f"(x)); return r;
}
__device__ __forceinline__ float ex2a(float x) {
    float r; asm("ex2.approx.f32 %0, %1;" : "=f"(r) : "f"(x)); return r;
}
__device__ __forceinline__ float sigm(float x) {           // 1/(1+2^(-x*log2e))
    return rcpa(1.0f + ex2a(-1.442695041f * x));
}
__device__ __forceinline__ float tanh_(float x) {          // 2*sigm(2x)-1
    return fmaf(2.0f, rcpa(1.0f + ex2a(-2.885390082f * x)), -1.0f);
}

// Shared memory layout (float units)
#define SM_W    0                    // 5*96*32 = 15360 (w_ih, natural layout)
#define SM_BR   (SM_W   + 15360)     // 160: b_ih+b_hh (r rows)
#define SM_BZ   (SM_BR  + 160)       // 160: b_ih+b_hh (z rows)
#define SM_BN   (SM_BZ  + 160)       // 160: b_ih (n rows)
#define SM_BHN  (SM_BN  + 160)       // 160: b_hh (n rows)
#define SM_FW   (SM_BHN + 160)       // 1024: fc_w
#define SM_FB   (SM_FW  + 1024)      // 32
#define SM_HB   (SM_FB  + 32)        // 1024 slots * 34 floats (pad 34: 8B-aligned rows)
#define SM_FLOATS (SM_HB + 1024*34)
#define SMEM_BYTES (SM_FLOATS * sizeof(float))   // 207,488 B

__global__ void __launch_bounds__(TPB, 1) gru4(
    const float* __restrict__ x,
    const float* __restrict__ w_ih,
    const float* __restrict__ b_ih,
    const float* __restrict__ b_hh,
    const float* __restrict__ fc_w,
    const float* __restrict__ fc_b,
    float* __restrict__ out)
{
    extern __shared__ float sm[];
    float* SW  = sm + SM_W;
    float* BR  = sm + SM_BR;
    float* BZ  = sm + SM_BZ;
    float* BN  = sm + SM_BN;
    float* BHN = sm + SM_BHN;
    float* FW  = sm + SM_FW;
    float* FB  = sm + SM_FB;
    float* HB  = sm + SM_HB;

    const int tid = threadIdx.x;

    // ---- cooperative preload (weights kept in natural packed layout) ----
    {
        const float4* src = (const float4*)w_ih;
        float4* dst = (float4*)SW;
        for (int i = tid; i < 15360 / 4; i += TPB) dst[i] = src[i];
    }
    for (int i = tid; i < NLAYERS * H; i += TPB) {
        int l = i >> 5, j = i & 31;
        BR[i]  = b_ih[l * 96 + j]      + b_hh[l * 96 + j];
        BZ[i]  = b_ih[l * 96 + 32 + j] + b_hh[l * 96 + 32 + j];
        BN[i]  = b_ih[l * 96 + 64 + j];
        BHN[i] = b_hh[l * 96 + 64 + j];
    }
    {
        const float4* src = (const float4*)fc_w;
        float4* dst = (float4*)FW;
        for (int i = tid; i < 1024 / 4; i += TPB) dst[i] = src[i];
    }
    if (tid < E) FB[tid] = fc_b[tid];
    __syncthreads();

    // ---- 4 batch elements per thread (interleaved by TPB: coalesced) ----
    const size_t base = (size_t)blockIdx.x * (4 * TPB) + tid;

    ull v[4][16];   // per element: 16 packed (x[2c], x[2c+1]) pairs
#pragma unroll
    for (int k = 0; k < 4; k++) {
        const ulonglong2* xp = (const ulonglong2*)(x + (base + (size_t)k * TPB) * E);
#pragma unroll
        for (int c = 0; c < 8; c++) {
            ulonglong2 t = xp[c];
            v[k][2 * c] = t.x; v[k][2 * c + 1] = t.y;
        }
    }

    // ---- 5 fused GRU layers (h0 = 0: w_hh path collapses to b_hh) ----
    for (int l = 0; l < NLAYERS; l++) {
        const float* SWl = SW + l * 3072;
        const float* brp  = BR  + l * H;
        const float* bzp  = BZ  + l * H;
        const float* bnp  = BN  + l * H;
        const float* bhnp = BHN + l * H;
#pragma unroll 1
        for (int j = 0; j < H; j++) {
            // gate rows are 32 floats each: r row j, z row 32+j, n row 64+j
            const ulonglong2* Wr = (const ulonglong2*)(SWl + (size_t)j * H);
            const ulonglong2* Wz = (const ulonglong2*)(SWl + (size_t)(32 + j) * H);
            const ulonglong2* Wn = (const ulonglong2*)(SWl + (size_t)(64 + j) * H);
            ull ar[4] = {0,0,0,0}, az[4] = {0,0,0,0}, an[4] = {0,0,0,0};
#pragma unroll
            for (int c = 0; c < 8; c++) {
                ulonglong2 wr = Wr[c];   // two packed weight pairs, no splat
                ulonglong2 wz = Wz[c];
                ulonglong2 wn = Wn[c];
#pragma unroll
                for (int k = 0; k < 4; k++) {
                    ar[k] = fma2(wr.x, v[k][2 * c], ar[k]);
                    ar[k] = fma2(wr.y, v[k][2 * c + 1], ar[k]);
                    az[k] = fma2(wz.x, v[k][2 * c], az[k]);
                    az[k] = fma2(wz.y, v[k][2 * c + 1], az[k]);
                    an[k] = fma2(wn.x, v[k][2 * c], an[k]);
                    an[k] = fma2(wn.y, v[k][2 * c + 1], an[k]);
                }
            }
            const float br = brp[j], bz = bzp[j], bn = bnp[j], bh = bhnp[j];
#pragma unroll
            for (int k = 0; k < 4; k++) {
                float a0, a1;
                unpack2(ar[k], a0, a1); float r = sigm(a0 + a1 + br);
                unpack2(az[k], a0, a1); float z = sigm(a0 + a1 + bz);
                unpack2(an[k], a0, a1); float n = tanh_(a0 + a1 + bn + r * bh);
                HB[(tid + k * TPB) * 34 + j] = (1.0f - z) * n;
            }
        }
        // reload new hidden state as packed pairs (own slots: no barrier needed)
#pragma unroll
        for (int k = 0; k < 4; k++) {
            const ull* hp = (const ull*)(HB + (tid + k * TPB) * 34);
#pragma unroll
            for (int c = 0; c < 16; c++) v[k][c] = hp[c];
        }
    }

    // ---- FC epilogue: out = fc_w . h + fc_b, float4 stores ----
#pragma unroll 1
    for (int eg = 0; eg < 8; eg++) {
        float o[4][4];
#pragma unroll
        for (int t = 0; t < 4; t++) {
            const int e = eg * 4 + t;
            const ulonglong2* Fw = (const ulonglong2*)(FW + (size_t)e * H);
            ull acc[4] = {0,0,0,0};
#pragma unroll
            for (int c = 0; c < 8; c++) {
                ulonglong2 w = Fw[c];
#pragma unroll
                for (int k = 0; k < 4; k++) {
                    acc[k] = fma2(w.x, v[k][2 * c], acc[k]);
                    acc[k] = fma2(w.y, v[k][2 * c + 1], acc[k]);
                }
            }
            const float fb = FB[e];
#pragma unroll
            for (int k = 0; k < 4; k++) {
                float a0, a1; unpack2(acc[k], a0, a1);
                o[k][t] = a0 + a1 + fb;
            }
        }
#pragma unroll
        for (int k = 0; k < 4; k++) {
            *(float4*)(out + (base + (size_t)k * TPB) * E + eg * 4) =
                make_float4(o[k][0], o[k][1], o[k][2], o[k][3]);
        }
    }
}

extern "C" void kernel_launch(void* const* d_in, const int* in_sizes, int n_in,
                              void* d_out, int out_size)
{
    const float* x    = (const float*)d_in[0];
    const float* w_ih = (const float*)d_in[1];
    // d_in[2] = w_hh: provably unused (h0 == 0 for every layer, T == 1)
    const float* b_ih = (const float*)d_in[3];
    const float* b_hh = (const float*)d_in[4];
    const float* fc_w = (const float*)d_in[5];
    const float* fc_b = (const float*)d_in[6];
    float* out = (float*)d_out;

    const int B = in_sizes[0] / E;                 // 1,048,576
    cudaFuncSetAttribute(gru4, cudaFuncAttributeMaxDynamicSharedMemorySize,
                         (int)SMEM_BYTES);
    const int grid = B / (4 * TPB);                // 1024 blocks, exact
    gru4<<<grid, TPB, SMEM_BYTES>>>(x, w_ih, b_ih, b_hh, fc_w, fc_b, out);
}